// round 10
// baseline (speedup 1.0000x reference)
#include <cuda_runtime.h>
#include <cstdint>

#define NEG (-1e30f)
#define TLAST 512
#define NQ4 8404992          /* 513*65536/4 */

// ---- k_scan shared memory layout (byte offsets) ----
#define OFF_TILE 0            /* 2 x 32768 : double-buffered tiles     */
#define OFF_RX   65536        /* 2 x 256 floats: DSMEM exchange bufs   */
#define OFF_XM   67584        /* 2 exchange mbarriers                  */
#define OFF_TM   67600        /* 2 tile mbarriers                      */
#define OFF_BT   67616        /* 130816 B viterbi backtrack            */
#define SCAN_SMEM (OFF_BT + 511 * 256)   /* 198432 */

// ---------------- device globals (no allocations allowed) ----------------
__device__ float4 g_expM4[NQ4];          // exp(logM), row-major   (beta, p12)
__device__ float4 g_expMT4[NQ4];         // exp(logM), transposed  (alpha)
__device__ float g_ua[514 * 256];        // normalized alpha mantissas
__device__ float g_vb[514 * 256];        // normalized beta  mantissas
__device__ int   g_Ea[514];
__device__ int   g_Eb[514];
__device__ float g_Zm;
__device__ int   g_Ez;
__device__ __align__(16) unsigned char g_idx[511 * 256];

// ------- kernel 1: logM = sum_k w_k f[k] (masked); emit expM, expMT, logMT --
// grid = 513 * 16 blocks; each block does one 64x64 tile of one t.
// d_out receives TRANSPOSED logM (only viterbi reads it; p12 overwrites later).
__global__ void __launch_bounds__(256) k_logM(const float4* __restrict__ f4,
                                              const float* __restrict__ w,
                                              float4* __restrict__ outT) {
    __shared__ float sL[64 * 65];
    __shared__ float sE[64 * 65];
    __shared__ float sw[4];
    if (threadIdx.x < 4) sw[threadIdx.x] = w[threadIdx.x];
    __syncthreads();
    const int blk = blockIdx.x;
    const int t  = blk >> 4;
    const int ti = (blk >> 2) & 3;
    const int tj = blk & 3;
    const int c4 = threadIdx.x & 15;      // float4 column within 64-wide tile
    const int r0 = threadIdx.x >> 4;      // 0..15
    const int jg4 = tj * 16 + c4;         // global float4 column
#pragma unroll
    for (int rr = 0; rr < 4; ++rr) {
        const int lr = r0 + rr * 16;
        const int i  = ti * 64 + lr;
        const size_t e = (size_t)t * 16384 + (size_t)i * 64 + jg4;
        float4 a = f4[e];
        float4 b = f4[e + (size_t)NQ4];
        float4 c = f4[e + 2 * (size_t)NQ4];
        float4 d = f4[e + 3 * (size_t)NQ4];
        float4 r;
        r.x = fmaf(sw[3], d.x, fmaf(sw[2], c.x, fmaf(sw[1], b.x, sw[0] * a.x)));
        r.y = fmaf(sw[3], d.y, fmaf(sw[2], c.y, fmaf(sw[1], b.y, sw[0] * a.y)));
        r.z = fmaf(sw[3], d.z, fmaf(sw[2], c.z, fmaf(sw[1], b.z, sw[0] * a.z)));
        r.w = fmaf(sw[3], d.w, fmaf(sw[2], c.w, fmaf(sw[1], b.w, sw[0] * a.w)));
        if (t == 0 && i != 0) { r.x = NEG; r.y = NEG; r.z = NEG; r.w = NEG; }
        if (t == TLAST) {
            if (jg4 != 0) { r.x = NEG; r.y = NEG; r.z = NEG; r.w = NEG; }
            else          { r.y = NEG; r.z = NEG; r.w = NEG; }
        }
        float4 ex;
        ex.x = __expf(r.x); ex.y = __expf(r.y); ex.z = __expf(r.z); ex.w = __expf(r.w);
        g_expM4[e] = ex;
        sL[lr * 65 + c4 * 4 + 0] = r.x;  sE[lr * 65 + c4 * 4 + 0] = ex.x;
        sL[lr * 65 + c4 * 4 + 1] = r.y;  sE[lr * 65 + c4 * 4 + 1] = ex.y;
        sL[lr * 65 + c4 * 4 + 2] = r.z;  sE[lr * 65 + c4 * 4 + 2] = ex.z;
        sL[lr * 65 + c4 * 4 + 3] = r.w;  sE[lr * 65 + c4 * 4 + 3] = ex.w;
    }
    __syncthreads();
#pragma unroll
    for (int rr = 0; rr < 4; ++rr) {
        const int jl = r0 + rr * 16;      // local row of transposed tile
        const size_t o = (size_t)t * 16384 + (size_t)(tj * 64 + jl) * 64 + ti * 16 + c4;
        float4 rl, re;
        rl.x = sL[(c4 * 4 + 0) * 65 + jl];  re.x = sE[(c4 * 4 + 0) * 65 + jl];
        rl.y = sL[(c4 * 4 + 1) * 65 + jl];  re.y = sE[(c4 * 4 + 1) * 65 + jl];
        rl.z = sL[(c4 * 4 + 2) * 65 + jl];  re.z = sE[(c4 * 4 + 2) * 65 + jl];
        rl.w = sL[(c4 * 4 + 3) * 65 + jl];  re.w = sE[(c4 * 4 + 3) * 65 + jl];
        outT[o]     = rl;
        g_expMT4[o] = re;
    }
}

// ---------------- PTX helpers ----------------
__device__ __forceinline__ uint32_t smem_u32(const void* p) {
    uint32_t a;
    asm("{ .reg .u64 t; cvta.to.shared.u64 t, %1; cvt.u32.u64 %0, t; }" : "=r"(a) : "l"(p));
    return a;
}
__device__ __forceinline__ uint32_t mapa_u32(uint32_t a, uint32_t rank) {
    uint32_t r;
    asm("mapa.shared::cluster.u32 %0, %1, %2;" : "=r"(r) : "r"(a), "r"(rank));
    return r;
}
__device__ __forceinline__ void st_remote_f32(uint32_t a, float v) {
    asm volatile("st.shared::cluster.f32 [%0], %1;" :: "r"(a), "f"(v) : "memory");
}
__device__ __forceinline__ void mbar_arrive_remote(uint32_t a) {
    asm volatile("mbarrier.arrive.release.cluster.shared::cluster.b64 _, [%0];"
                 :: "r"(a) : "memory");
}
__device__ __forceinline__ void mbar_init(uint32_t a, uint32_t cnt) {
    asm volatile("mbarrier.init.shared.b64 [%0], %1;" :: "r"(a), "r"(cnt) : "memory");
}
__device__ __forceinline__ void mbar_wait(uint32_t a, uint32_t parity) {
    asm volatile(
        "{\n\t.reg .pred P;\n"
        "W%=:\n\t"
        "mbarrier.try_wait.parity.acquire.cluster.shared::cta.b64 P, [%0], %1, 0x989680;\n\t"
        "@!P bra W%=;\n\t}"
        :: "r"(a), "r"(parity) : "memory");
}
__device__ __forceinline__ void expect_tx(uint32_t mbar, uint32_t bytes) {
    asm volatile("mbarrier.arrive.expect_tx.shared.b64 _, [%0], %1;"
                 :: "r"(mbar), "r"(bytes) : "memory");
}
__device__ __forceinline__ void bulk_g2s(uint32_t dst, const void* src,
                                         uint32_t bytes, uint32_t mbar) {
    asm volatile(
        "cp.async.bulk.shared::cluster.global.mbarrier::complete_tx::bytes [%0], [%1], %2, [%3];"
        :: "r"(dst), "l"(src), "r"(bytes), "r"(mbar) : "memory");
}
__device__ __forceinline__ void cluster_sync_all() {
    asm volatile("barrier.cluster.arrive.aligned;" ::: "memory");
    asm volatile("barrier.cluster.wait.aligned;" ::: "memory");
}

// ---------------- kernel 2: the three scans --------------------------------
// grid = 24 CTAs, cluster (8,1,1): cluster 0 = alpha, 1 = beta, 2 = viterbi
__global__ void __cluster_dims__(8, 1, 1) __launch_bounds__(256, 1)
k_scan(const float* __restrict__ lMT, float* __restrict__ path_out) {
    extern __shared__ unsigned char smem_raw[];
    float* s_rx = reinterpret_cast<float*>(smem_raw + OFF_RX);
    unsigned char* s_bt = smem_raw + OFF_BT;

    const int tid   = threadIdx.x;
    const int role  = blockIdx.x >> 3;
    const int crank = blockIdx.x & 7;
    const uint32_t sbase = smem_u32(smem_raw);
    const int lane = tid & 31;
    const int wrp  = tid >> 5;

    if (tid == 0) {
        mbar_init(sbase + OFF_XM + 0, 8);   // exchange: one arrive per CTA
        mbar_init(sbase + OFF_XM + 8, 8);
        mbar_init(sbase + OFF_TM + 0, 1);   // tiles: expect_tx pattern
        mbar_init(sbase + OFF_TM + 8, 1);
    }
    __syncthreads();
    cluster_sync_all();            // all peers' mbarriers initialized

    uint32_t pb[8];
#pragma unroll
    for (int p = 0; p < 8; ++p) pb[p] = mapa_u32(sbase, p);

    if (role == 0) {
        // ============ forward alpha scan (linear space, 2^k renorm) ============
        const int part  = tid & 7;
        const int jloc  = tid >> 3;
        const int jbase = crank * 32;
        const float* src = reinterpret_cast<const float*>(g_expMT4);
        s_rx[256 + tid] = (tid == 0) ? 1.f : 0.f;   // v0 in buffer 1
        int Ea = 0;
        __syncthreads();
        if (tid == 0) {
            expect_tx(sbase + OFF_TM + 0, 32768);
            bulk_g2s(sbase + OFF_TILE, src + (size_t)jbase * 256, 32768, sbase + OFF_TM + 0);
            expect_tx(sbase + OFF_TM + 8, 32768);
            bulk_g2s(sbase + OFF_TILE + 32768, src + 65536 + (size_t)jbase * 256, 32768,
                     sbase + OFF_TM + 8);
        }
        for (int t = 0; t <= TLAST; ++t) {
            const int buf = t & 1;
            const int tp  = (t >> 1) & 1;
            const int rb  = ((t + 1) & 1) * 256;
            mbar_wait(sbase + OFF_TM + buf * 8, tp);
            float S0 = s_rx[rb];
            int e0 = (__float_as_int(S0) >> 23) - 127;
            float scale = __int_as_float((127 - e0) << 23);   // exact 2^-e0
            Ea += e0;
            if (wrp == crank)
                g_ua[(size_t)t * 256 + jbase + lane] = s_rx[rb + jbase + lane] * scale;
            if (crank == 0 && tid == 0) g_Ea[t] = Ea;
            const float4* T = reinterpret_cast<const float4*>(smem_raw + OFF_TILE + buf * 32768)
                              + jloc * 64 + part;
            float acc = 0.f;
#pragma unroll
            for (int m = 0; m < 8; ++m) {
                float4 tv = T[m * 8];
                const float4 av = *reinterpret_cast<const float4*>(s_rx + rb + m * 32 + part * 4);
                acc = fmaf(tv.x, av.x, acc);
                acc = fmaf(tv.y, av.y, acc);
                acc = fmaf(tv.z, av.z, acc);
                acc = fmaf(tv.w, av.w, acc);
            }
            acc *= scale;
            acc += __shfl_xor_sync(0xffffffffu, acc, 1);
            acc += __shfl_xor_sync(0xffffffffu, acc, 2);
            acc += __shfl_xor_sync(0xffffffffu, acc, 4);
            if (part == 0) {
                uint32_t orx = OFF_RX + (uint32_t)buf * 1024 + (uint32_t)(jbase + jloc) * 4;
#pragma unroll
                for (int p = 0; p < 8; ++p) st_remote_f32(pb[p] + orx, acc);
            }
            __syncthreads();
            if (t + 2 <= TLAST && tid == 0) {
                expect_tx(sbase + OFF_TM + buf * 8, 32768);
                bulk_g2s(sbase + OFF_TILE + buf * 32768,
                         src + (size_t)(t + 2) * 65536 + (size_t)jbase * 256, 32768,
                         sbase + OFF_TM + buf * 8);
            }
            if (tid < 8) mbar_arrive_remote(pb[tid] + OFF_XM + buf * 8);
            mbar_wait(sbase + OFF_XM + buf * 8, tp);
        }
        // tail: v_{513} sits in buffer (512&1)=0
        {
            float S0 = s_rx[0];
            int e0 = (__float_as_int(S0) >> 23) - 127;
            float scale = __int_as_float((127 - e0) << 23);
            Ea += e0;
            if (wrp == crank)
                g_ua[513 * 256 + jbase + lane] = s_rx[jbase + lane] * scale;
            if (crank == 0 && tid == 0) {
                g_Ea[513] = Ea;
                float Zm = 0.f;
                for (int j = 0; j < 256; ++j) Zm += s_rx[j] * scale;
                g_Zm = Zm;
                g_Ez = Ea;
            }
        }
    } else if (role == 1) {
        // ============ backward beta scan (linear space, 2^k renorm) ============
        const int jq    = tid & 7;
        const int iloc  = tid >> 3;
        const int ibase = crank * 32;
        const float* src = reinterpret_cast<const float*>(g_expM4);
        s_rx[256 + tid] = (tid == 0) ? 1.f : 0.f;   // beta_{513} in buffer 1
        int Eb = 0;
        __syncthreads();
        if (tid == 0) {
            expect_tx(sbase + OFF_TM + 0, 32768);
            bulk_g2s(sbase + OFF_TILE, src + (size_t)TLAST * 65536 + (size_t)ibase * 256,
                     32768, sbase + OFF_TM + 0);
            expect_tx(sbase + OFF_TM + 8, 32768);
            bulk_g2s(sbase + OFF_TILE + 32768,
                     src + (size_t)(TLAST - 1) * 65536 + (size_t)ibase * 256, 32768,
                     sbase + OFF_TM + 8);
        }
        for (int k = 0; k <= TLAST; ++k) {
            const int t   = TLAST - k;
            const int buf = k & 1;
            const int tp  = (k >> 1) & 1;
            const int rb  = ((k + 1) & 1) * 256;
            mbar_wait(sbase + OFF_TM + buf * 8, tp);
            float S0 = s_rx[rb];
            int e0 = (__float_as_int(S0) >> 23) - 127;
            float scale = __int_as_float((127 - e0) << 23);
            Eb += e0;
            if (wrp == crank)
                g_vb[(size_t)(t + 1) * 256 + ibase + lane] = s_rx[rb + ibase + lane] * scale;
            if (crank == 0 && tid == 0) g_Eb[t + 1] = Eb;
            const float4* T = reinterpret_cast<const float4*>(smem_raw + OFF_TILE + buf * 32768)
                              + iloc * 64 + jq;
            float acc = 0.f;
#pragma unroll
            for (int m = 0; m < 8; ++m) {
                float4 tv = T[m * 8];
                const float4 bv = *reinterpret_cast<const float4*>(s_rx + rb + m * 32 + jq * 4);
                acc = fmaf(tv.x, bv.x, acc);
                acc = fmaf(tv.y, bv.y, acc);
                acc = fmaf(tv.z, bv.z, acc);
                acc = fmaf(tv.w, bv.w, acc);
            }
            acc *= scale;
            acc += __shfl_xor_sync(0xffffffffu, acc, 1);
            acc += __shfl_xor_sync(0xffffffffu, acc, 2);
            acc += __shfl_xor_sync(0xffffffffu, acc, 4);
            if (jq == 0) {
                uint32_t orx = OFF_RX + (uint32_t)buf * 1024 + (uint32_t)(ibase + iloc) * 4;
#pragma unroll
                for (int p = 0; p < 8; ++p) st_remote_f32(pb[p] + orx, acc);
            }
            __syncthreads();
            if (t >= 2 && tid == 0) {
                expect_tx(sbase + OFF_TM + buf * 8, 32768);
                bulk_g2s(sbase + OFF_TILE + buf * 32768,
                         src + (size_t)(t - 2) * 65536 + (size_t)ibase * 256, 32768,
                         sbase + OFF_TM + buf * 8);
            }
            if (tid < 8) mbar_arrive_remote(pb[tid] + OFF_XM + buf * 8);
            mbar_wait(sbase + OFF_XM + buf * 8, tp);
        }
        // tail: beta_0 sits in buffer (512&1)=0
        {
            float S0 = s_rx[0];
            int e0 = (__float_as_int(S0) >> 23) - 127;
            float scale = __int_as_float((127 - e0) << 23);
            Eb += e0;
            if (wrp == crank)
                g_vb[ibase + lane] = s_rx[ibase + lane] * scale;
            if (crank == 0 && tid == 0) g_Eb[0] = Eb;
        }
    } else {
        // ============ viterbi (max-plus, exact log space) + backtrack ============
        const int part  = tid & 7;
        const int jloc  = tid >> 3;
        const int jbase = crank * 32;
        s_rx[256 + tid] = lMT[(size_t)tid * 256];   // delta0[j] = logMT[0][j][0]
        __syncthreads();
        if (tid == 0) {
            expect_tx(sbase + OFF_TM + 0, 32768);
            bulk_g2s(sbase + OFF_TILE, lMT + 65536 + (size_t)jbase * 256, 32768,
                     sbase + OFF_TM + 0);
            expect_tx(sbase + OFF_TM + 8, 32768);
            bulk_g2s(sbase + OFF_TILE + 32768, lMT + 2 * 65536 + (size_t)jbase * 256, 32768,
                     sbase + OFF_TM + 8);
        }
        for (int s = 1; s <= 511; ++s) {
            const int k   = s - 1;
            const int buf = k & 1;
            const int tp  = (k >> 1) & 1;
            const int rb  = ((k + 1) & 1) * 256;
            mbar_wait(sbase + OFF_TM + buf * 8, tp);
            const float4* T = reinterpret_cast<const float4*>(smem_raw + OFF_TILE + buf * 32768)
                              + jloc * 64 + part;
            float bv = -__int_as_float(0x7f800000);
            int bi = 0;
#pragma unroll
            for (int m = 0; m < 8; ++m) {
                float4 tv = T[m * 8];
                const float4 dv = *reinterpret_cast<const float4*>(s_rx + rb + m * 32 + part * 4);
                const int ib = m * 32 + part * 4;
                float c0 = dv.x + tv.x; if (c0 > bv) { bv = c0; bi = ib; }
                float c1 = dv.y + tv.y; if (c1 > bv) { bv = c1; bi = ib + 1; }
                float c2 = dv.z + tv.z; if (c2 > bv) { bv = c2; bi = ib + 2; }
                float c3 = dv.w + tv.w; if (c3 > bv) { bv = c3; bi = ib + 3; }
            }
            // merge over 'part' with explicit first-max (min-i on ties)
#pragma unroll
            for (int off = 1; off <= 4; off <<= 1) {
                float ov = __shfl_xor_sync(0xffffffffu, bv, off);
                int   oi = __shfl_xor_sync(0xffffffffu, bi, off);
                if (ov > bv || (ov == bv && oi < bi)) { bv = ov; bi = oi; }
            }
            if (part == 0) {
                g_idx[(size_t)k * 256 + jbase + jloc] = (unsigned char)bi;
                uint32_t orx = OFF_RX + (uint32_t)buf * 1024 + (uint32_t)(jbase + jloc) * 4;
#pragma unroll
                for (int p = 0; p < 8; ++p) st_remote_f32(pb[p] + orx, bv);
            }
            __syncthreads();
            if (s + 2 <= 511 && tid == 0) {
                expect_tx(sbase + OFF_TM + buf * 8, 32768);
                bulk_g2s(sbase + OFF_TILE + buf * 32768,
                         lMT + (size_t)(s + 2) * 65536 + (size_t)jbase * 256, 32768,
                         sbase + OFF_TM + buf * 8);
            }
            if (tid < 8) mbar_arrive_remote(pb[tid] + OFF_XM + buf * 8);
            mbar_wait(sbase + OFF_XM + buf * 8, tp);
        }
        cluster_sync_all();     // peers' g_idx stores visible to crank 0
        if (crank == 0) {
            const uint32_t* srcb = reinterpret_cast<const uint32_t*>(g_idx);
            uint32_t* dst = reinterpret_cast<uint32_t*>(s_bt);
            for (int k2 = tid; k2 < (511 * 256) / 4; k2 += 256) dst[k2] = srcb[k2];
            __syncthreads();
            if (tid == 0) {
                // final delta in buffer (510&1)=0
                float bv = s_rx[0];
                int li = 0;
                for (int j = 1; j < 256; ++j) {
                    float v = s_rx[j];
                    if (v > bv) { bv = v; li = j; }
                }
                path_out[511] = (float)li;
                int y = li;
                for (int s2 = 510; s2 >= 0; --s2) {
                    y = s_bt[s2 * 256 + y];
                    path_out[s2] = (float)y;
                }
            }
        }
    }
}

// ------- kernel 3: p12 = expM * u[t][i] * v[t+1][j] * 2^E / Zm (no scan dep) --
__global__ void k_p12(float4* __restrict__ m) {
    int e = blockIdx.x * blockDim.x + threadIdx.x;
    if (e >= NQ4) return;
    int t  = e >> 14;
    int q  = e & 16383;
    int i  = q >> 6;
    int j4 = q & 63;
    float4 v = g_expM4[e];
    float ui = g_ua[t * 256 + i];
    const float4 B = *reinterpret_cast<const float4*>(&g_vb[(t + 1) * 256 + j4 * 4]);
    int E = g_Ea[t] + g_Eb[t + 1] - g_Ez;
    float a = ui * ldexpf(__fdividef(1.0f, g_Zm), E);
    float4 r;
    r.x = v.x * a * B.x;
    r.y = v.y * a * B.y;
    r.z = v.z * a * B.z;
    r.w = v.w * a * B.w;
    m[e] = r;
}

// ---------------- launcher ----------------
extern "C" void kernel_launch(void* const* d_in, const int* in_sizes, int n_in,
                              void* d_out, int out_size) {
    const float* f = (const float*)d_in[0];
    const float* w = (const float*)d_in[1];
    float* out = (float*)d_out;

    cudaFuncSetAttribute(k_scan, cudaFuncAttributeMaxDynamicSharedMemorySize, SCAN_SMEM);

    k_logM<<<513 * 16, 256>>>((const float4*)f, w, (float4*)out);
    k_scan<<<24, 256, SCAN_SMEM>>>(out, out + (out_size - 512));
    const int nb = (NQ4 + 255) / 256;   // 32832
    k_p12<<<nb, 256>>>((float4*)out);
}

// round 11
// speedup vs baseline: 1.6694x; 1.6694x over previous
#include <cuda_runtime.h>
#include <cstdint>

#define NEG (-1e30f)
#define TLAST 512
#define NQ4 8404992          /* 513*65536/4 */

// ---- k_scan shared memory layout (byte offsets) ----
#define OFF_TILE 0            /* 2 x 32768 : double-buffered tiles     */
#define OFF_RX   65536        /* 2 x 256 floats: st.async exchange     */
#define OFF_XM   67584        /* 2 exchange mbarriers                  */
#define OFF_TM   67600        /* 2 tile mbarriers                      */
#define OFF_BT   67616        /* 130816 B viterbi backtrack            */
#define SCAN_SMEM (OFF_BT + 511 * 256)   /* 198432 */

// ---------------- device globals (no allocations allowed) ----------------
__device__ float4 g_expM4[NQ4];          // exp(logM), row-major   (beta, p12)
__device__ float4 g_expMT4[NQ4];         // exp(logM), transposed  (alpha)
__device__ float g_ua[514 * 256];        // normalized alpha mantissas
__device__ float g_vb[514 * 256];        // normalized beta  mantissas
__device__ int   g_Ea[514];
__device__ int   g_Eb[514];
__device__ float g_Zm;
__device__ int   g_Ez;
__device__ __align__(16) unsigned char g_idx[511 * 256];

// ------- kernel 1: logM = sum_k w_k f[k] (masked); emit expM, expMT, logMT --
// grid = 513 * 16 blocks; each block does one 64x64 tile of one t.
// d_out receives TRANSPOSED logM (only viterbi reads it; p12 overwrites later).
__global__ void __launch_bounds__(256) k_logM(const float4* __restrict__ f4,
                                              const float* __restrict__ w,
                                              float4* __restrict__ outT) {
    __shared__ float sL[64 * 65];
    __shared__ float sE[64 * 65];
    __shared__ float sw[4];
    if (threadIdx.x < 4) sw[threadIdx.x] = w[threadIdx.x];
    __syncthreads();
    const int blk = blockIdx.x;
    const int t  = blk >> 4;
    const int ti = (blk >> 2) & 3;
    const int tj = blk & 3;
    const int c4 = threadIdx.x & 15;      // float4 column within 64-wide tile
    const int r0 = threadIdx.x >> 4;      // 0..15
    const int jg4 = tj * 16 + c4;         // global float4 column
#pragma unroll
    for (int rr = 0; rr < 4; ++rr) {
        const int lr = r0 + rr * 16;
        const int i  = ti * 64 + lr;
        const size_t e = (size_t)t * 16384 + (size_t)i * 64 + jg4;
        float4 a = f4[e];
        float4 b = f4[e + (size_t)NQ4];
        float4 c = f4[e + 2 * (size_t)NQ4];
        float4 d = f4[e + 3 * (size_t)NQ4];
        float4 r;
        r.x = fmaf(sw[3], d.x, fmaf(sw[2], c.x, fmaf(sw[1], b.x, sw[0] * a.x)));
        r.y = fmaf(sw[3], d.y, fmaf(sw[2], c.y, fmaf(sw[1], b.y, sw[0] * a.y)));
        r.z = fmaf(sw[3], d.z, fmaf(sw[2], c.z, fmaf(sw[1], b.z, sw[0] * a.z)));
        r.w = fmaf(sw[3], d.w, fmaf(sw[2], c.w, fmaf(sw[1], b.w, sw[0] * a.w)));
        if (t == 0 && i != 0) { r.x = NEG; r.y = NEG; r.z = NEG; r.w = NEG; }
        if (t == TLAST) {
            if (jg4 != 0) { r.x = NEG; r.y = NEG; r.z = NEG; r.w = NEG; }
            else          { r.y = NEG; r.z = NEG; r.w = NEG; }
        }
        float4 ex;
        ex.x = __expf(r.x); ex.y = __expf(r.y); ex.z = __expf(r.z); ex.w = __expf(r.w);
        g_expM4[e] = ex;
        sL[lr * 65 + c4 * 4 + 0] = r.x;  sE[lr * 65 + c4 * 4 + 0] = ex.x;
        sL[lr * 65 + c4 * 4 + 1] = r.y;  sE[lr * 65 + c4 * 4 + 1] = ex.y;
        sL[lr * 65 + c4 * 4 + 2] = r.z;  sE[lr * 65 + c4 * 4 + 2] = ex.z;
        sL[lr * 65 + c4 * 4 + 3] = r.w;  sE[lr * 65 + c4 * 4 + 3] = ex.w;
    }
    __syncthreads();
#pragma unroll
    for (int rr = 0; rr < 4; ++rr) {
        const int jl = r0 + rr * 16;      // local row of transposed tile
        const size_t o = (size_t)t * 16384 + (size_t)(tj * 64 + jl) * 64 + ti * 16 + c4;
        float4 rl, re;
        rl.x = sL[(c4 * 4 + 0) * 65 + jl];  re.x = sE[(c4 * 4 + 0) * 65 + jl];
        rl.y = sL[(c4 * 4 + 1) * 65 + jl];  re.y = sE[(c4 * 4 + 1) * 65 + jl];
        rl.z = sL[(c4 * 4 + 2) * 65 + jl];  re.z = sE[(c4 * 4 + 2) * 65 + jl];
        rl.w = sL[(c4 * 4 + 3) * 65 + jl];  re.w = sE[(c4 * 4 + 3) * 65 + jl];
        outT[o]     = rl;
        g_expMT4[o] = re;
    }
}

// ---------------- PTX helpers ----------------
__device__ __forceinline__ uint32_t smem_u32(const void* p) {
    uint32_t a;
    asm("{ .reg .u64 t; cvta.to.shared.u64 t, %1; cvt.u32.u64 %0, t; }" : "=r"(a) : "l"(p));
    return a;
}
__device__ __forceinline__ uint32_t mapa_u32(uint32_t a, uint32_t rank) {
    uint32_t r;
    asm("mapa.shared::cluster.u32 %0, %1, %2;" : "=r"(r) : "r"(a), "r"(rank));
    return r;
}
// fire-and-forget remote store; completion accounted as tx bytes at the
// REMOTE mbarrier — no release fence, no store-drain on the producer.
__device__ __forceinline__ void st_async_f32(uint32_t raddr, float v, uint32_t rmbar) {
    asm volatile(
        "st.async.shared::cluster.mbarrier::complete_tx::bytes.b32 [%0], %1, [%2];"
        :: "r"(raddr), "r"(__float_as_uint(v)), "r"(rmbar) : "memory");
}
__device__ __forceinline__ void mbar_init(uint32_t a, uint32_t cnt) {
    asm volatile("mbarrier.init.shared.b64 [%0], %1;" :: "r"(a), "r"(cnt) : "memory");
}
__device__ __forceinline__ void mbar_wait(uint32_t a, uint32_t parity) {
    asm volatile(
        "{\n\t.reg .pred P;\n"
        "W%=:\n\t"
        "mbarrier.try_wait.parity.acquire.cluster.shared::cta.b64 P, [%0], %1, 0x989680;\n\t"
        "@!P bra W%=;\n\t}"
        :: "r"(a), "r"(parity) : "memory");
}
__device__ __forceinline__ void expect_tx(uint32_t mbar, uint32_t bytes) {
    asm volatile("mbarrier.arrive.expect_tx.shared.b64 _, [%0], %1;"
                 :: "r"(mbar), "r"(bytes) : "memory");
}
__device__ __forceinline__ void bulk_g2s(uint32_t dst, const void* src,
                                         uint32_t bytes, uint32_t mbar) {
    asm volatile(
        "cp.async.bulk.shared::cluster.global.mbarrier::complete_tx::bytes [%0], [%1], %2, [%3];"
        :: "r"(dst), "l"(src), "r"(bytes), "r"(mbar) : "memory");
}
__device__ __forceinline__ void cluster_sync_all() {
    asm volatile("barrier.cluster.arrive.aligned;" ::: "memory");
    asm volatile("barrier.cluster.wait.aligned;" ::: "memory");
}

// ---------------- kernel 2: the three scans --------------------------------
// grid = 24 CTAs, cluster (8,1,1): cluster 0 = alpha, 1 = beta, 2 = viterbi
__global__ void __cluster_dims__(8, 1, 1) __launch_bounds__(256, 1)
k_scan(const float* __restrict__ lMT, float* __restrict__ path_out) {
    extern __shared__ unsigned char smem_raw[];
    float* s_rx = reinterpret_cast<float*>(smem_raw + OFF_RX);
    unsigned char* s_bt = smem_raw + OFF_BT;

    const int tid   = threadIdx.x;
    const int role  = blockIdx.x >> 3;
    const int crank = blockIdx.x & 7;
    const uint32_t sbase = smem_u32(smem_raw);
    const int lane = tid & 31;
    const int wrp  = tid >> 5;

    if (tid == 0) {
        mbar_init(sbase + OFF_XM + 0, 1);   // exchange: tx-byte accounting
        mbar_init(sbase + OFF_XM + 8, 1);
        mbar_init(sbase + OFF_TM + 0, 1);   // tiles: expect_tx pattern
        mbar_init(sbase + OFF_TM + 8, 1);
    }
    __syncthreads();
    cluster_sync_all();            // all peers' mbarriers initialized

    uint32_t pb[8];
#pragma unroll
    for (int p = 0; p < 8; ++p) pb[p] = mapa_u32(sbase, p);

    if (role == 0) {
        // ============ forward alpha scan (linear space, 2^k renorm) ============
        const int part  = tid & 7;
        const int jloc  = tid >> 3;
        const int jbase = crank * 32;
        const float* src = reinterpret_cast<const float*>(g_expMT4);
        s_rx[256 + tid] = (tid == 0) ? 1.f : 0.f;   // v0 in buffer 1
        int Ea = 0;
        __syncthreads();
        if (tid == 0) {
            expect_tx(sbase + OFF_TM + 0, 32768);
            bulk_g2s(sbase + OFF_TILE, src + (size_t)jbase * 256, 32768, sbase + OFF_TM + 0);
            expect_tx(sbase + OFF_TM + 8, 32768);
            bulk_g2s(sbase + OFF_TILE + 32768, src + 65536 + (size_t)jbase * 256, 32768,
                     sbase + OFF_TM + 8);
        }
        for (int t = 0; t <= TLAST; ++t) {
            const int buf = t & 1;
            const int tp  = (t >> 1) & 1;
            const int rb  = ((t + 1) & 1) * 256;
            mbar_wait(sbase + OFF_TM + buf * 8, tp);
            float S0 = s_rx[rb];
            int e0 = (__float_as_int(S0) >> 23) - 127;
            float scale = __int_as_float((127 - e0) << 23);   // exact 2^-e0
            Ea += e0;
            if (wrp == crank)
                g_ua[(size_t)t * 256 + jbase + lane] = s_rx[rb + jbase + lane] * scale;
            if (crank == 0 && tid == 0) g_Ea[t] = Ea;
            const float4* T = reinterpret_cast<const float4*>(smem_raw + OFF_TILE + buf * 32768)
                              + jloc * 64 + part;
            float acc = 0.f;
#pragma unroll
            for (int m = 0; m < 8; ++m) {
                float4 tv = T[m * 8];
                const float4 av = *reinterpret_cast<const float4*>(s_rx + rb + m * 32 + part * 4);
                acc = fmaf(tv.x, av.x, acc);
                acc = fmaf(tv.y, av.y, acc);
                acc = fmaf(tv.z, av.z, acc);
                acc = fmaf(tv.w, av.w, acc);
            }
            acc *= scale;
            acc += __shfl_xor_sync(0xffffffffu, acc, 1);
            acc += __shfl_xor_sync(0xffffffffu, acc, 2);
            acc += __shfl_xor_sync(0xffffffffu, acc, 4);
            __syncthreads();   // all reads of tile[buf] and s_rx[buf] done
            if (tid == 0) expect_tx(sbase + OFF_XM + buf * 8, 1024);
            if (part == 0) {
                const uint32_t orx = OFF_RX + (uint32_t)buf * 1024 + (uint32_t)(jbase + jloc) * 4;
                const uint32_t omb = OFF_XM + (uint32_t)buf * 8;
#pragma unroll
                for (int p = 0; p < 8; ++p) st_async_f32(pb[p] + orx, acc, pb[p] + omb);
            }
            if (t + 2 <= TLAST && tid == 0) {
                expect_tx(sbase + OFF_TM + buf * 8, 32768);
                bulk_g2s(sbase + OFF_TILE + buf * 32768,
                         src + (size_t)(t + 2) * 65536 + (size_t)jbase * 256, 32768,
                         sbase + OFF_TM + buf * 8);
            }
            mbar_wait(sbase + OFF_XM + buf * 8, tp);
        }
        // tail: v_{513} sits in buffer (512&1)=0
        {
            float S0 = s_rx[0];
            int e0 = (__float_as_int(S0) >> 23) - 127;
            float scale = __int_as_float((127 - e0) << 23);
            Ea += e0;
            if (wrp == crank)
                g_ua[513 * 256 + jbase + lane] = s_rx[jbase + lane] * scale;
            if (crank == 0 && tid == 0) {
                g_Ea[513] = Ea;
                float Zm = 0.f;
                for (int j = 0; j < 256; ++j) Zm += s_rx[j] * scale;
                g_Zm = Zm;
                g_Ez = Ea;
            }
        }
    } else if (role == 1) {
        // ============ backward beta scan (linear space, 2^k renorm) ============
        const int jq    = tid & 7;
        const int iloc  = tid >> 3;
        const int ibase = crank * 32;
        const float* src = reinterpret_cast<const float*>(g_expM4);
        s_rx[256 + tid] = (tid == 0) ? 1.f : 0.f;   // beta_{513} in buffer 1
        int Eb = 0;
        __syncthreads();
        if (tid == 0) {
            expect_tx(sbase + OFF_TM + 0, 32768);
            bulk_g2s(sbase + OFF_TILE, src + (size_t)TLAST * 65536 + (size_t)ibase * 256,
                     32768, sbase + OFF_TM + 0);
            expect_tx(sbase + OFF_TM + 8, 32768);
            bulk_g2s(sbase + OFF_TILE + 32768,
                     src + (size_t)(TLAST - 1) * 65536 + (size_t)ibase * 256, 32768,
                     sbase + OFF_TM + 8);
        }
        for (int k = 0; k <= TLAST; ++k) {
            const int t   = TLAST - k;
            const int buf = k & 1;
            const int tp  = (k >> 1) & 1;
            const int rb  = ((k + 1) & 1) * 256;
            mbar_wait(sbase + OFF_TM + buf * 8, tp);
            float S0 = s_rx[rb];
            int e0 = (__float_as_int(S0) >> 23) - 127;
            float scale = __int_as_float((127 - e0) << 23);
            Eb += e0;
            if (wrp == crank)
                g_vb[(size_t)(t + 1) * 256 + ibase + lane] = s_rx[rb + ibase + lane] * scale;
            if (crank == 0 && tid == 0) g_Eb[t + 1] = Eb;
            const float4* T = reinterpret_cast<const float4*>(smem_raw + OFF_TILE + buf * 32768)
                              + iloc * 64 + jq;
            float acc = 0.f;
#pragma unroll
            for (int m = 0; m < 8; ++m) {
                float4 tv = T[m * 8];
                const float4 bv = *reinterpret_cast<const float4*>(s_rx + rb + m * 32 + jq * 4);
                acc = fmaf(tv.x, bv.x, acc);
                acc = fmaf(tv.y, bv.y, acc);
                acc = fmaf(tv.z, bv.z, acc);
                acc = fmaf(tv.w, bv.w, acc);
            }
            acc *= scale;
            acc += __shfl_xor_sync(0xffffffffu, acc, 1);
            acc += __shfl_xor_sync(0xffffffffu, acc, 2);
            acc += __shfl_xor_sync(0xffffffffu, acc, 4);
            __syncthreads();
            if (tid == 0) expect_tx(sbase + OFF_XM + buf * 8, 1024);
            if (jq == 0) {
                const uint32_t orx = OFF_RX + (uint32_t)buf * 1024 + (uint32_t)(ibase + iloc) * 4;
                const uint32_t omb = OFF_XM + (uint32_t)buf * 8;
#pragma unroll
                for (int p = 0; p < 8; ++p) st_async_f32(pb[p] + orx, acc, pb[p] + omb);
            }
            if (t >= 2 && tid == 0) {
                expect_tx(sbase + OFF_TM + buf * 8, 32768);
                bulk_g2s(sbase + OFF_TILE + buf * 32768,
                         src + (size_t)(t - 2) * 65536 + (size_t)ibase * 256, 32768,
                         sbase + OFF_TM + buf * 8);
            }
            mbar_wait(sbase + OFF_XM + buf * 8, tp);
        }
        // tail: beta_0 sits in buffer (512&1)=0
        {
            float S0 = s_rx[0];
            int e0 = (__float_as_int(S0) >> 23) - 127;
            float scale = __int_as_float((127 - e0) << 23);
            Eb += e0;
            if (wrp == crank)
                g_vb[ibase + lane] = s_rx[ibase + lane] * scale;
            if (crank == 0 && tid == 0) g_Eb[0] = Eb;
        }
    } else {
        // ============ viterbi (max-plus, exact log space) + backtrack ============
        const int part  = tid & 7;
        const int jloc  = tid >> 3;
        const int jbase = crank * 32;
        s_rx[256 + tid] = lMT[(size_t)tid * 256];   // delta0[j] = logMT[0][j][0]
        __syncthreads();
        if (tid == 0) {
            expect_tx(sbase + OFF_TM + 0, 32768);
            bulk_g2s(sbase + OFF_TILE, lMT + 65536 + (size_t)jbase * 256, 32768,
                     sbase + OFF_TM + 0);
            expect_tx(sbase + OFF_TM + 8, 32768);
            bulk_g2s(sbase + OFF_TILE + 32768, lMT + 2 * 65536 + (size_t)jbase * 256, 32768,
                     sbase + OFF_TM + 8);
        }
        for (int s = 1; s <= 511; ++s) {
            const int k   = s - 1;
            const int buf = k & 1;
            const int tp  = (k >> 1) & 1;
            const int rb  = ((k + 1) & 1) * 256;
            mbar_wait(sbase + OFF_TM + buf * 8, tp);
            const float4* T = reinterpret_cast<const float4*>(smem_raw + OFF_TILE + buf * 32768)
                              + jloc * 64 + part;
            float bv = -__int_as_float(0x7f800000);
            int bi = 0;
#pragma unroll
            for (int m = 0; m < 8; ++m) {
                float4 tv = T[m * 8];
                const float4 dv = *reinterpret_cast<const float4*>(s_rx + rb + m * 32 + part * 4);
                const int ib = m * 32 + part * 4;
                float c0 = dv.x + tv.x; if (c0 > bv) { bv = c0; bi = ib; }
                float c1 = dv.y + tv.y; if (c1 > bv) { bv = c1; bi = ib + 1; }
                float c2 = dv.z + tv.z; if (c2 > bv) { bv = c2; bi = ib + 2; }
                float c3 = dv.w + tv.w; if (c3 > bv) { bv = c3; bi = ib + 3; }
            }
            // merge over 'part' with explicit first-max (min-i on ties)
#pragma unroll
            for (int off = 1; off <= 4; off <<= 1) {
                float ov = __shfl_xor_sync(0xffffffffu, bv, off);
                int   oi = __shfl_xor_sync(0xffffffffu, bi, off);
                if (ov > bv || (ov == bv && oi < bi)) { bv = ov; bi = oi; }
            }
            __syncthreads();
            if (tid == 0) expect_tx(sbase + OFF_XM + buf * 8, 1024);
            if (part == 0) {
                g_idx[(size_t)k * 256 + jbase + jloc] = (unsigned char)bi;
                const uint32_t orx = OFF_RX + (uint32_t)buf * 1024 + (uint32_t)(jbase + jloc) * 4;
                const uint32_t omb = OFF_XM + (uint32_t)buf * 8;
#pragma unroll
                for (int p = 0; p < 8; ++p) st_async_f32(pb[p] + orx, bv, pb[p] + omb);
            }
            if (s + 2 <= 511 && tid == 0) {
                expect_tx(sbase + OFF_TM + buf * 8, 32768);
                bulk_g2s(sbase + OFF_TILE + buf * 32768,
                         lMT + (size_t)(s + 2) * 65536 + (size_t)jbase * 256, 32768,
                         sbase + OFF_TM + buf * 8);
            }
            mbar_wait(sbase + OFF_XM + buf * 8, tp);
        }
        cluster_sync_all();     // peers' g_idx stores visible to crank 0
        if (crank == 0) {
            const uint32_t* srcb = reinterpret_cast<const uint32_t*>(g_idx);
            uint32_t* dst = reinterpret_cast<uint32_t*>(s_bt);
            for (int k2 = tid; k2 < (511 * 256) / 4; k2 += 256) dst[k2] = srcb[k2];
            __syncthreads();
            if (tid == 0) {
                // final delta in buffer (510&1)=0
                float bv = s_rx[0];
                int li = 0;
                for (int j = 1; j < 256; ++j) {
                    float v = s_rx[j];
                    if (v > bv) { bv = v; li = j; }
                }
                path_out[511] = (float)li;
                int y = li;
                for (int s2 = 510; s2 >= 0; --s2) {
                    y = s_bt[s2 * 256 + y];
                    path_out[s2] = (float)y;
                }
            }
        }
    }
}

// ------- kernel 3: p12 = expM * u[t][i] * v[t+1][j] * 2^E / Zm (no scan dep) --
__global__ void k_p12(float4* __restrict__ m) {
    int e = blockIdx.x * blockDim.x + threadIdx.x;
    if (e >= NQ4) return;
    int t  = e >> 14;
    int q  = e & 16383;
    int i  = q >> 6;
    int j4 = q & 63;
    float4 v = g_expM4[e];
    float ui = g_ua[t * 256 + i];
    const float4 B = *reinterpret_cast<const float4*>(&g_vb[(t + 1) * 256 + j4 * 4]);
    int E = g_Ea[t] + g_Eb[t + 1] - g_Ez;
    float a = ui * ldexpf(__fdividef(1.0f, g_Zm), E);
    float4 r;
    r.x = v.x * a * B.x;
    r.y = v.y * a * B.y;
    r.z = v.z * a * B.z;
    r.w = v.w * a * B.w;
    m[e] = r;
}

// ---------------- launcher ----------------
extern "C" void kernel_launch(void* const* d_in, const int* in_sizes, int n_in,
                              void* d_out, int out_size) {
    const float* f = (const float*)d_in[0];
    const float* w = (const float*)d_in[1];
    float* out = (float*)d_out;

    cudaFuncSetAttribute(k_scan, cudaFuncAttributeMaxDynamicSharedMemorySize, SCAN_SMEM);

    k_logM<<<513 * 16, 256>>>((const float4*)f, w, (float4*)out);
    k_scan<<<24, 256, SCAN_SMEM>>>(out, out + (out_size - 512));
    const int nb = (NQ4 + 255) / 256;   // 32832
    k_p12<<<nb, 256>>>((float4*)out);
}